// round 1
// baseline (speedup 1.0000x reference)
#include <cuda_runtime.h>
#include <cuda_bf16.h>
#include <cstdint>

// Problem constants
#define B_DIM   256
#define D_DIM   256
#define N_DIM   131072
#define TEMP_INV 20.0f      // 1/0.05
#define EPS_SM  1e-6f
#define EPS_LOG 1e-6f

#define NTILE   64                  // N columns per CTA tile
#define NTILES  (N_DIM / NTILE)     // 2048
#define LDA     264                 // 256 + 8 pad (bf16 elems)
#define LDB     264
#define MAX_G   512

// Device scratch (allocation-free rule: __device__ globals)
__device__ __align__(16) __nv_bfloat16 g_A[B_DIM * D_DIM];                 // inputs*20, bf16
__device__ __align__(16) __nv_bfloat16 g_cfb[(size_t)N_DIM * D_DIM];       // cluster feats bf16 (64MB)
__device__ float g_partial[MAX_G * B_DIM];
__device__ float g_tdot[B_DIM];

// ---------------- helpers ----------------
__device__ __forceinline__ void ldm4(uint32_t &r0, uint32_t &r1, uint32_t &r2, uint32_t &r3,
                                     uint32_t addr) {
    asm volatile("ldmatrix.sync.aligned.m8n8.x4.shared.b16 {%0,%1,%2,%3}, [%4];\n"
                 : "=r"(r0), "=r"(r1), "=r"(r2), "=r"(r3) : "r"(addr));
}

__device__ __forceinline__ void mma_bf16(float *c, const uint32_t *a, const uint32_t *b) {
    asm volatile("mma.sync.aligned.m16n8k16.row.col.f32.bf16.bf16.f32 "
                 "{%0,%1,%2,%3}, {%4,%5,%6,%7}, {%8,%9}, {%0,%1,%2,%3};\n"
                 : "+f"(c[0]), "+f"(c[1]), "+f"(c[2]), "+f"(c[3])
                 : "r"(a[0]), "r"(a[1]), "r"(a[2]), "r"(a[3]), "r"(b[0]), "r"(b[1]));
}

__device__ __forceinline__ void cp16(uint32_t dst, const void *src) {
    asm volatile("cp.async.cg.shared.global [%0], [%1], 16;\n" :: "r"(dst), "l"(src));
}

// ---------------- prep kernels ----------------
__global__ void prep_inputs_kernel(const float4 *__restrict__ in) {
    int i = blockIdx.x * blockDim.x + threadIdx.x;   // 16384 float4s
    float4 v = in[i];
    __nv_bfloat162 lo = __floats2bfloat162_rn(v.x * TEMP_INV, v.y * TEMP_INV);
    __nv_bfloat162 hi = __floats2bfloat162_rn(v.z * TEMP_INV, v.w * TEMP_INV);
    uint2 u;
    u.x = *reinterpret_cast<uint32_t *>(&lo);
    u.y = *reinterpret_cast<uint32_t *>(&hi);
    reinterpret_cast<uint2 *>(g_A)[i] = u;
}

__global__ void prep_cf_kernel(const float4 *__restrict__ in) {
    int i = blockIdx.x * blockDim.x + threadIdx.x;   // 8388608 float4s
    float4 v = in[i];
    __nv_bfloat162 lo = __floats2bfloat162_rn(v.x, v.y);
    __nv_bfloat162 hi = __floats2bfloat162_rn(v.z, v.w);
    uint2 u;
    u.x = *reinterpret_cast<uint32_t *>(&lo);
    u.y = *reinterpret_cast<uint32_t *>(&hi);
    reinterpret_cast<uint2 *>(g_cfb)[i] = u;
}

// exact fp32 dot for the target column (matches reference precision where it matters)
__global__ void targets_kernel(const float *__restrict__ inputs,
                               const float *__restrict__ cf,
                               const int *__restrict__ indexes,
                               const int *__restrict__ labels) {
    int lane = threadIdx.x & 31;
    int w = (blockIdx.x * blockDim.x + threadIdx.x) >> 5;   // 0..255
    if (w >= B_DIM) return;
    int t = labels[indexes[w]];
    const float4 *a = reinterpret_cast<const float4 *>(inputs + (size_t)w * D_DIM);
    const float4 *b = reinterpret_cast<const float4 *>(cf + (size_t)t * D_DIM);
    float s = 0.f;
#pragma unroll
    for (int i = 0; i < 2; i++) {
        float4 x = a[lane + i * 32];
        float4 y = b[lane + i * 32];
        s += x.x * y.x + x.y * y.y + x.z * y.z + x.w * y.w;
    }
#pragma unroll
    for (int o = 16; o; o >>= 1) s += __shfl_xor_sync(0xffffffffu, s, o);
    if (lane == 0) g_tdot[w] = s * TEMP_INV;
}

// ---------------- main GEMM + exp + rowsum ----------------
__device__ __forceinline__ void issueB(int tile, uint32_t dstBase, int tid) {
    const __nv_bfloat16 *src = g_cfb + (size_t)tile * NTILE * D_DIM;
#pragma unroll
    for (int i = 0; i < 8; i++) {
        int c = tid + i * 256;            // 0..2047 chunks of 16B
        int row = c >> 5;                 // 0..63
        int koff = (c & 31) << 3;         // 0..248
        cp16(dstBase + (uint32_t)((row * LDB + koff) * 2), src + row * D_DIM + koff);
    }
}

__global__ void __launch_bounds__(256, 1) gemm_kernel() {
    extern __shared__ char smem[];
    __nv_bfloat16 *sA = reinterpret_cast<__nv_bfloat16 *>(smem);                 // 256*264
    __nv_bfloat16 *sB = reinterpret_cast<__nv_bfloat16 *>(smem + B_DIM * LDA * 2);
    float *sp = reinterpret_cast<float *>(smem + B_DIM * LDA * 2 + 2 * NTILE * LDB * 2);

    const int tid = threadIdx.x;
    const int lane = tid & 31;
    const int warp = tid >> 5;
    const int warpM = warp & 3;   // 0..3 -> m base = warpM*64
    const int warpN = warp >> 2;  // 0..1 -> n base = warpN*32

    // Load A (bf16, pre-scaled) into padded smem
#pragma unroll
    for (int i = 0; i < 32; i++) {
        int idx = tid + i * 256;          // 8192 uint4 chunks
        int row = idx >> 5;
        int col = (idx & 31) << 3;
        *reinterpret_cast<uint4 *>(sA + row * LDA + col) =
            reinterpret_cast<const uint4 *>(g_A)[idx];
    }

    const uint32_t sA32 = (uint32_t)__cvta_generic_to_shared(sA);
    const uint32_t sB32 = (uint32_t)__cvta_generic_to_shared(sB);
    const uint32_t BUFB = NTILE * LDB * 2;   // 33792 bytes per B buffer

    const int sub = lane >> 3, r = lane & 7;
    const uint32_t aBase =
        sA32 + (uint32_t)(((warpM * 64 + (sub & 1) * 8 + r) * LDA + (sub >> 1) * 8) * 2);
    const uint32_t bBase0 =
        sB32 + (uint32_t)(((warpN * 32 + (sub >> 1) * 8 + r) * LDB + (sub & 1) * 8) * 2);

    float rsum[4][2];
#pragma unroll
    for (int mt = 0; mt < 4; mt++) { rsum[mt][0] = 0.f; rsum[mt][1] = 0.f; }

    int tile = blockIdx.x;
    int buf = 0;
    if (tile < NTILES) issueB(tile, sB32, tid);
    asm volatile("cp.async.commit_group;\n" ::: "memory");

    for (; tile < NTILES; tile += gridDim.x) {
        int nxt = tile + gridDim.x;
        if (nxt < NTILES) issueB(nxt, sB32 + (buf ^ 1) * BUFB, tid);
        asm volatile("cp.async.commit_group;\n" ::: "memory");
        asm volatile("cp.async.wait_group 1;\n" ::: "memory");
        __syncthreads();

        float acc[4][4][4];
#pragma unroll
        for (int mt = 0; mt < 4; mt++)
#pragma unroll
            for (int nt = 0; nt < 4; nt++)
#pragma unroll
                for (int q = 0; q < 4; q++) acc[mt][nt][q] = 0.f;

        const uint32_t bBase = bBase0 + buf * BUFB;
#pragma unroll
        for (int ks = 0; ks < 16; ks++) {
            uint32_t a[4][4], b[4][2];
#pragma unroll
            for (int mt = 0; mt < 4; mt++)
                ldm4(a[mt][0], a[mt][1], a[mt][2], a[mt][3],
                     aBase + (uint32_t)(mt * 16 * LDA * 2 + ks * 32));
            {
                uint32_t r0, r1, r2, r3;
                ldm4(r0, r1, r2, r3, bBase + (uint32_t)(ks * 32));
                b[0][0] = r0; b[0][1] = r1; b[1][0] = r2; b[1][1] = r3;
                ldm4(r0, r1, r2, r3, bBase + (uint32_t)(16 * LDB * 2 + ks * 32));
                b[2][0] = r0; b[2][1] = r1; b[3][0] = r2; b[3][1] = r3;
            }
#pragma unroll
            for (int mt = 0; mt < 4; mt++)
#pragma unroll
                for (int nt = 0; nt < 4; nt++)
                    mma_bf16(acc[mt][nt], a[mt], b[nt]);
        }

        // fused exp + per-row partial sums (logits already scaled by 1/TEMP)
#pragma unroll
        for (int mt = 0; mt < 4; mt++) {
            float lo = 0.f, hi = 0.f;
#pragma unroll
            for (int nt = 0; nt < 4; nt++) {
                lo += __expf(acc[mt][nt][0]) + __expf(acc[mt][nt][1]);
                hi += __expf(acc[mt][nt][2]) + __expf(acc[mt][nt][3]);
            }
            rsum[mt][0] += lo;
            rsum[mt][1] += hi;
        }
        __syncthreads();   // protect sB before next overwrite
        buf ^= 1;
    }

    // reduce across the quad (cols within n8), then combine the two warpN halves
#pragma unroll
    for (int mt = 0; mt < 4; mt++)
#pragma unroll
        for (int h = 0; h < 2; h++) {
            float v = rsum[mt][h];
            v += __shfl_xor_sync(0xffffffffu, v, 1);
            v += __shfl_xor_sync(0xffffffffu, v, 2);
            if ((lane & 3) == 0)
                sp[warpN * 256 + warpM * 64 + mt * 16 + h * 8 + (lane >> 2)] = v;
        }
    __syncthreads();
    g_partial[blockIdx.x * B_DIM + tid] = sp[tid] + sp[256 + tid];
}

// ---------------- final reduction ----------------
__global__ void finalize_kernel(int G, float *__restrict__ out) {
    int m = threadIdx.x;   // 256 threads
    float S = 0.f;
    for (int g = 0; g < G; g++) S += g_partial[g * B_DIM + m];   // fixed order: deterministic
    float lt = g_tdot[m];
    float p = expf(lt) / (S + EPS_SM) + EPS_LOG;
    float v = logf(p);
    __shared__ float red[256];
    red[m] = v;
    __syncthreads();
#pragma unroll
    for (int s = 128; s > 0; s >>= 1) {
        if (m < s) red[m] += red[m + s];
        __syncthreads();
    }
    if (m == 0) out[0] = -red[0] / (float)B_DIM;
}

// ---------------- launch ----------------
extern "C" void kernel_launch(void *const *d_in, const int *in_sizes, int n_in,
                              void *d_out, int out_size) {
    const float *inputs = (const float *)d_in[0];
    const float *cf     = (const float *)d_in[1];
    // d_in[2] instance_features: unused by the reference loss
    const int *indexes  = (const int *)d_in[3];
    const int *labels   = (const int *)d_in[4];
    float *out          = (float *)d_out;

    int dev = 0;
    cudaGetDevice(&dev);
    int sm = 148;
    cudaDeviceGetAttribute(&sm, cudaDevAttrMultiProcessorCount, dev);
    int G = sm;
    if (G < 1) G = 148;
    if (G > MAX_G) G = MAX_G;

    const int smemBytes = B_DIM * LDA * 2 + 2 * NTILE * LDB * 2 + 512 * 4;  // 204800
    cudaFuncSetAttribute(gemm_kernel, cudaFuncAttributeMaxDynamicSharedMemorySize, smemBytes);

    prep_inputs_kernel<<<64, 256>>>((const float4 *)inputs);
    prep_cf_kernel<<<32768, 256>>>((const float4 *)cf);
    targets_kernel<<<32, 256>>>(inputs, cf, indexes, labels);
    gemm_kernel<<<G, 256, smemBytes>>>();
    finalize_kernel<<<1, 256>>>(G, out);
}

// round 3
// speedup vs baseline: 1.2200x; 1.2200x over previous
#include <cuda_runtime.h>
#include <cuda_bf16.h>
#include <cstdint>

// Problem constants
#define B_DIM   256
#define D_DIM   256
#define N_DIM   131072
#define TEMP_INV 20.0f
#define LOG2E   1.4426950408889634f
#define EPS_SM  1e-6f
#define EPS_LOG 1e-6f

#define NTILE   64                  // N columns per CTA tile
#define NTILES  (N_DIM / NTILE)     // 2048
#define LDA     264                 // 256 + 8 pad (bf16 elems)
#define LDB     264
#define MAX_G   512

// Device scratch
__device__ __align__(16) __nv_bfloat16 g_A[B_DIM * D_DIM];  // inputs * TEMP_INV * LOG2E
__device__ float g_partial[MAX_G * B_DIM];
__device__ float g_tdot[B_DIM];

// ---------------- helpers ----------------
__device__ __forceinline__ void ldm4(uint32_t &r0, uint32_t &r1, uint32_t &r2, uint32_t &r3,
                                     uint32_t addr) {
    asm volatile("ldmatrix.sync.aligned.m8n8.x4.shared.b16 {%0,%1,%2,%3}, [%4];\n"
                 : "=r"(r0), "=r"(r1), "=r"(r2), "=r"(r3) : "r"(addr));
}

__device__ __forceinline__ void mma_bf16(float *c, const uint32_t *a, const uint32_t *b) {
    asm volatile("mma.sync.aligned.m16n8k16.row.col.f32.bf16.bf16.f32 "
                 "{%0,%1,%2,%3}, {%4,%5,%6,%7}, {%8,%9}, {%0,%1,%2,%3};\n"
                 : "+f"(c[0]), "+f"(c[1]), "+f"(c[2]), "+f"(c[3])
                 : "r"(a[0]), "r"(a[1]), "r"(a[2]), "r"(a[3]), "r"(b[0]), "r"(b[1]));
}

__device__ __forceinline__ float ex2(float x) {
    float y;
    asm("ex2.approx.f32 %0, %1;" : "=f"(y) : "f"(x));
    return y;
}

// ---------------- prep: inputs f32 -> bf16 (x TEMP_INV*LOG2E) ----------------
__global__ void prep_inputs_kernel(const float4 *__restrict__ in) {
    int i = blockIdx.x * blockDim.x + threadIdx.x;   // 16384 float4s
    const float S = TEMP_INV * LOG2E;
    float4 v = in[i];
    __nv_bfloat162 lo = __floats2bfloat162_rn(v.x * S, v.y * S);
    __nv_bfloat162 hi = __floats2bfloat162_rn(v.z * S, v.w * S);
    uint2 u;
    u.x = *reinterpret_cast<uint32_t *>(&lo);
    u.y = *reinterpret_cast<uint32_t *>(&hi);
    reinterpret_cast<uint2 *>(g_A)[i] = u;
}

// exact fp32 dot for the target column
__global__ void targets_kernel(const float *__restrict__ inputs,
                               const float *__restrict__ cf,
                               const int *__restrict__ indexes,
                               const int *__restrict__ labels) {
    int lane = threadIdx.x & 31;
    int w = (blockIdx.x * blockDim.x + threadIdx.x) >> 5;
    if (w >= B_DIM) return;
    int t = labels[indexes[w]];
    const float4 *a = reinterpret_cast<const float4 *>(inputs + (size_t)w * D_DIM);
    const float4 *b = reinterpret_cast<const float4 *>(cf + (size_t)t * D_DIM);
    float s = 0.f;
#pragma unroll
    for (int i = 0; i < 2; i++) {
        float4 x = a[lane + i * 32];
        float4 y = b[lane + i * 32];
        s += x.x * y.x + x.y * y.y + x.z * y.z + x.w * y.w;
    }
#pragma unroll
    for (int o = 16; o; o >>= 1) s += __shfl_xor_sync(0xffffffffu, s, o);
    if (lane == 0) g_tdot[w] = s * TEMP_INV;
}

// ---------------- fused GEMM + exp + rowsum ----------------
__global__ void __launch_bounds__(256, 1) gemm_kernel(const float *__restrict__ cf) {
    extern __shared__ char smem[];
    __nv_bfloat16 *sA = reinterpret_cast<__nv_bfloat16 *>(smem);                 // 256*264
    __nv_bfloat16 *sB = reinterpret_cast<__nv_bfloat16 *>(smem + B_DIM * LDA * 2);
    float *sp = reinterpret_cast<float *>(smem + B_DIM * LDA * 2 + 2 * NTILE * LDB * 2);

    const int tid = threadIdx.x;
    const int lane = tid & 31;
    const int warp = tid >> 5;
    const int warpM = warp & 3;   // m base = warpM*64
    const int warpN = warp >> 2;  // n base = warpN*32
    const int G = gridDim.x, bid = blockIdx.x;
    const float4 *cfv = reinterpret_cast<const float4 *>(cf);

    // B fill coords for this thread (16 chunks of 4 f32 per tile)
    // chunk c = tid + it*256: row r = c>>6 (0..63), k quad = (c&63)*4
    // ---- load A (pre-scaled bf16) into padded smem ----
#pragma unroll
    for (int i = 0; i < 32; i++) {
        int idx = tid + i * 256;
        int row = idx >> 5;
        int col = (idx & 31) << 3;
        *reinterpret_cast<uint4 *>(sA + row * LDA + col) =
            reinterpret_cast<const uint4 *>(g_A)[idx];
    }

    // ---- preload tile(bid) into buf 0 ----
    {
        const size_t rowbase = (size_t)bid * NTILE;
#pragma unroll
        for (int it = 0; it < 16; it++) {
            int c = tid + it * 256;
            int r = c >> 6;
            int kq = c & 63;
            float4 v = cfv[(rowbase + r) * (D_DIM / 4) + kq];
            __nv_bfloat162 lo = __floats2bfloat162_rn(v.x, v.y);
            __nv_bfloat162 hi = __floats2bfloat162_rn(v.z, v.w);
            uint2 u;
            u.x = *reinterpret_cast<uint32_t *>(&lo);
            u.y = *reinterpret_cast<uint32_t *>(&hi);
            *reinterpret_cast<uint2 *>(sB + r * LDB + kq * 4) = u;
        }
    }

    const uint32_t sA32 = (uint32_t)__cvta_generic_to_shared(sA);
    const uint32_t sB32 = (uint32_t)__cvta_generic_to_shared(sB);
    const uint32_t BUFB = NTILE * LDB * 2;

    const int sub = lane >> 3, r8 = lane & 7;
    const uint32_t aBase =
        sA32 + (uint32_t)(((warpM * 64 + (sub & 1) * 8 + r8) * LDA + (sub >> 1) * 8) * 2);
    const uint32_t bBase0 =
        sB32 + (uint32_t)(((warpN * 32 + (sub >> 1) * 8 + r8) * LDB + (sub & 1) * 8) * 2);

    float rsum[4][2];
#pragma unroll
    for (int mt = 0; mt < 4; mt++) { rsum[mt][0] = 0.f; rsum[mt][1] = 0.f; }

    __syncthreads();

    int buf = 0;
    for (int tile = bid; tile < NTILES; tile += G) {
        const int nxt = tile + G;
        const bool have_next = (nxt < NTILES);

        // ---- issue next-tile B loads early (latency hides under MMA) ----
        float4 v[16];
        if (have_next) {
            const size_t rowbase = (size_t)nxt * NTILE;
#pragma unroll
            for (int it = 0; it < 16; it++) {
                int c = tid + it * 256;
                int r = c >> 6;
                int kq = c & 63;
                v[it] = cfv[(rowbase + r) * (D_DIM / 4) + kq];
            }
        }

        // ---- MMA on current buf ----
        float acc[4][4][4];
#pragma unroll
        for (int mt = 0; mt < 4; mt++)
#pragma unroll
            for (int nt = 0; nt < 4; nt++)
#pragma unroll
                for (int q = 0; q < 4; q++) acc[mt][nt][q] = 0.f;

        const uint32_t bBase = bBase0 + buf * BUFB;
#pragma unroll
        for (int ks = 0; ks < 16; ks++) {
            uint32_t a[4][4], b[4][2];
#pragma unroll
            for (int mt = 0; mt < 4; mt++)
                ldm4(a[mt][0], a[mt][1], a[mt][2], a[mt][3],
                     aBase + (uint32_t)(mt * 16 * LDA * 2 + ks * 32));
            {
                uint32_t q0, q1, q2, q3;
                ldm4(q0, q1, q2, q3, bBase + (uint32_t)(ks * 32));
                b[0][0] = q0; b[0][1] = q1; b[1][0] = q2; b[1][1] = q3;
                ldm4(q0, q1, q2, q3, bBase + (uint32_t)(16 * LDB * 2 + ks * 32));
                b[2][0] = q0; b[2][1] = q1; b[3][0] = q2; b[3][1] = q3;
            }
#pragma unroll
            for (int mt = 0; mt < 4; mt++)
#pragma unroll
                for (int nt = 0; nt < 4; nt++)
                    mma_bf16(acc[mt][nt], a[mt], b[nt]);
        }

        // ---- convert + store next tile into buf^1 ----
        if (have_next) {
            __nv_bfloat16 *dB = sB + (buf ^ 1) * (NTILE * LDB);
#pragma unroll
            for (int it = 0; it < 16; it++) {
                int c = tid + it * 256;
                int r = c >> 6;
                int kq = c & 63;
                __nv_bfloat162 lo = __floats2bfloat162_rn(v[it].x, v[it].y);
                __nv_bfloat162 hi = __floats2bfloat162_rn(v[it].z, v[it].w);
                uint2 u;
                u.x = *reinterpret_cast<uint32_t *>(&lo);
                u.y = *reinterpret_cast<uint32_t *>(&hi);
                *reinterpret_cast<uint2 *>(dB + r * LDB + kq * 4) = u;
            }
        }

        // ---- epilogue: acc holds logits*log2e -> ex2 + rowsum ----
#pragma unroll
        for (int mt = 0; mt < 4; mt++) {
            float lo = 0.f, hi = 0.f;
#pragma unroll
            for (int nt = 0; nt < 4; nt++) {
                lo += ex2(acc[mt][nt][0]) + ex2(acc[mt][nt][1]);
                hi += ex2(acc[mt][nt][2]) + ex2(acc[mt][nt][3]);
            }
            rsum[mt][0] += lo;
            rsum[mt][1] += hi;
        }

        __syncthreads();   // buf fully consumed + buf^1 fully written
        buf ^= 1;
    }

    // reduce across the quad, combine the two warpN halves
#pragma unroll
    for (int mt = 0; mt < 4; mt++)
#pragma unroll
        for (int h = 0; h < 2; h++) {
            float vv = rsum[mt][h];
            vv += __shfl_xor_sync(0xffffffffu, vv, 1);
            vv += __shfl_xor_sync(0xffffffffu, vv, 2);
            if ((lane & 3) == 0)
                sp[warpN * 256 + warpM * 64 + mt * 16 + h * 8 + (lane >> 2)] = vv;
        }
    __syncthreads();
    g_partial[bid * B_DIM + tid] = sp[tid] + sp[256 + tid];
}

// ---------------- final reduction ----------------
__global__ void finalize_kernel(int G, float *__restrict__ out) {
    int m = threadIdx.x;   // 256 threads
    float S = 0.f;
    for (int g = 0; g < G; g++) S += g_partial[g * B_DIM + m];   // fixed order
    float lt = g_tdot[m];
    float p = expf(lt) / (S + EPS_SM) + EPS_LOG;
    float vv = logf(p);
    __shared__ float red[256];
    red[m] = vv;
    __syncthreads();
#pragma unroll
    for (int s = 128; s > 0; s >>= 1) {
        if (m < s) red[m] += red[m + s];
        __syncthreads();
    }
    if (m == 0) out[0] = -red[0] / (float)B_DIM;
}

// ---------------- launch ----------------
extern "C" void kernel_launch(void *const *d_in, const int *in_sizes, int n_in,
                              void *d_out, int out_size) {
    const float *inputs = (const float *)d_in[0];
    const float *cf     = (const float *)d_in[1];
    // d_in[2] instance_features: unused by the reference loss
    const int *indexes  = (const int *)d_in[3];
    const int *labels   = (const int *)d_in[4];
    float *out          = (float *)d_out;

    int dev = 0;
    cudaGetDevice(&dev);
    int sm = 148;
    cudaDeviceGetAttribute(&sm, cudaDevAttrMultiProcessorCount, dev);
    int G = sm;
    if (G < 1) G = 148;
    if (G > MAX_G) G = MAX_G;
    if (G > NTILES) G = NTILES;

    const int smemBytes = B_DIM * LDA * 2 + 2 * NTILE * LDB * 2 + 512 * 4;  // 204800
    cudaFuncSetAttribute(gemm_kernel, cudaFuncAttributeMaxDynamicSharedMemorySize, smemBytes);

    prep_inputs_kernel<<<64, 256>>>((const float4 *)inputs);
    targets_kernel<<<32, 256>>>(inputs, cf, indexes, labels);
    gemm_kernel<<<G, 256, smemBytes>>>(cf);
    finalize_kernel<<<1, 256>>>(G, out);
}

// round 4
// speedup vs baseline: 1.2579x; 1.0310x over previous
#include <cuda_runtime.h>
#include <cuda_bf16.h>
#include <cstdint>

// Problem constants
#define B_DIM   256
#define D_DIM   256
#define N_DIM   131072
#define TEMP_INV 20.0f
#define LOG2E   1.4426950408889634f
#define EPS_SM  1e-6f
#define EPS_LOG 1e-6f

#define NTILE   64                  // N columns per CTA tile
#define NTILES  (N_DIM / NTILE)     // 2048
#define LDA     264                 // 256 + 8 pad (bf16 elems)
#define LDB     264
#define GSTRIDE 160                 // per-row stride in g_partial (>= max grid)

// Device scratch
__device__ __align__(16) __nv_bfloat16 g_A[B_DIM * D_DIM];  // inputs * TEMP_INV * LOG2E
__device__ __align__(16) float g_partial[B_DIM * GSTRIDE];  // [m][g] transposed
__device__ float g_tdot[B_DIM];

// ---------------- helpers ----------------
__device__ __forceinline__ void ldm4(uint32_t &r0, uint32_t &r1, uint32_t &r2, uint32_t &r3,
                                     uint32_t addr) {
    asm volatile("ldmatrix.sync.aligned.m8n8.x4.shared.b16 {%0,%1,%2,%3}, [%4];\n"
                 : "=r"(r0), "=r"(r1), "=r"(r2), "=r"(r3) : "r"(addr));
}

__device__ __forceinline__ void mma_bf16(float *c, const uint32_t *a, const uint32_t *b) {
    asm volatile("mma.sync.aligned.m16n8k16.row.col.f32.bf16.bf16.f32 "
                 "{%0,%1,%2,%3}, {%4,%5,%6,%7}, {%8,%9}, {%0,%1,%2,%3};\n"
                 : "+f"(c[0]), "+f"(c[1]), "+f"(c[2]), "+f"(c[3])
                 : "r"(a[0]), "r"(a[1]), "r"(a[2]), "r"(a[3]), "r"(b[0]), "r"(b[1]));
}

__device__ __forceinline__ float ex2(float x) {
    float y;
    asm("ex2.approx.f32 %0, %1;" : "=f"(y) : "f"(x));
    return y;
}

// ---------------- prep: inputs f32 -> bf16 (x TEMP_INV*LOG2E) ----------------
__global__ void prep_inputs_kernel(const float4 *__restrict__ in) {
    int i = blockIdx.x * blockDim.x + threadIdx.x;   // 16384 float4s
    const float S = TEMP_INV * LOG2E;
    float4 v = in[i];
    __nv_bfloat162 lo = __floats2bfloat162_rn(v.x * S, v.y * S);
    __nv_bfloat162 hi = __floats2bfloat162_rn(v.z * S, v.w * S);
    uint2 u;
    u.x = *reinterpret_cast<uint32_t *>(&lo);
    u.y = *reinterpret_cast<uint32_t *>(&hi);
    reinterpret_cast<uint2 *>(g_A)[i] = u;
}

// exact fp32 dot for the target column
__global__ void targets_kernel(const float *__restrict__ inputs,
                               const float *__restrict__ cf,
                               const int *__restrict__ indexes,
                               const int *__restrict__ labels) {
    int lane = threadIdx.x & 31;
    int w = (blockIdx.x * blockDim.x + threadIdx.x) >> 5;
    if (w >= B_DIM) return;
    int t = labels[indexes[w]];
    const float4 *a = reinterpret_cast<const float4 *>(inputs + (size_t)w * D_DIM);
    const float4 *b = reinterpret_cast<const float4 *>(cf + (size_t)t * D_DIM);
    float s = 0.f;
#pragma unroll
    for (int i = 0; i < 2; i++) {
        float4 x = a[lane + i * 32];
        float4 y = b[lane + i * 32];
        s += x.x * y.x + x.y * y.y + x.z * y.z + x.w * y.w;
    }
#pragma unroll
    for (int o = 16; o; o >>= 1) s += __shfl_xor_sync(0xffffffffu, s, o);
    if (lane == 0) g_tdot[w] = s * TEMP_INV;
}

// ---------------- producer: load+convert one B tile into smem buffer ----------------
static __device__ __forceinline__ void fill_B(const float4 *__restrict__ cfv, int tile,
                                              __nv_bfloat16 *dB, int ptid) {
    const size_t rowbase = (size_t)tile * NTILE;
#pragma unroll
    for (int it = 0; it < 16; it++) {
        int c = ptid + it * 256;       // 0..4095 float4 chunks
        int r = c >> 6;                // 0..63 (N row in tile)
        int kq = c & 63;               // 0..63 (K quad)
        float4 v = cfv[(rowbase + r) * (D_DIM / 4) + kq];
        __nv_bfloat162 lo = __floats2bfloat162_rn(v.x, v.y);
        __nv_bfloat162 hi = __floats2bfloat162_rn(v.z, v.w);
        uint2 u;
        u.x = *reinterpret_cast<uint32_t *>(&lo);
        u.y = *reinterpret_cast<uint32_t *>(&hi);
        *reinterpret_cast<uint2 *>(dB + r * LDB + kq * 4) = u;
    }
}

// ---------------- fused GEMM + exp + rowsum (producer/consumer warps) ----------------
__global__ void __launch_bounds__(512, 1) gemm_kernel(const float *__restrict__ cf) {
    extern __shared__ char smem[];
    __nv_bfloat16 *sA = reinterpret_cast<__nv_bfloat16 *>(smem);                 // 256*264
    __nv_bfloat16 *sB = reinterpret_cast<__nv_bfloat16 *>(smem + B_DIM * LDA * 2);
    float *sp = reinterpret_cast<float *>(smem + B_DIM * LDA * 2 + 2 * NTILE * LDB * 2);

    const int tid = threadIdx.x;
    const int lane = tid & 31;
    const int warp = tid >> 5;
    const bool producer = (warp >= 8);
    const int G = gridDim.x, bid = blockIdx.x;
    const float4 *cfv = reinterpret_cast<const float4 *>(cf);

    if (producer) {
        // fill first tile into buf 0 (256 producer threads)
        fill_B(cfv, bid, sB, tid - 256);
    } else {
        // load A (pre-scaled bf16) into padded smem
#pragma unroll
        for (int i = 0; i < 32; i++) {
            int idx = tid + i * 256;
            int row = idx >> 5;
            int col = (idx & 31) << 3;
            *reinterpret_cast<uint4 *>(sA + row * LDA + col) =
                reinterpret_cast<const uint4 *>(g_A)[idx];
        }
    }

    const uint32_t sA32 = (uint32_t)__cvta_generic_to_shared(sA);
    const uint32_t sB32 = (uint32_t)__cvta_generic_to_shared(sB);
    const uint32_t BUFB = NTILE * LDB * 2;

    const int warpM = warp & 3;
    const int warpN = (warp >> 2) & 1;
    const int sub = lane >> 3, r8 = lane & 7;
    const uint32_t aBase =
        sA32 + (uint32_t)(((warpM * 64 + (sub & 1) * 8 + r8) * LDA + (sub >> 1) * 8) * 2);
    const uint32_t bBase0 =
        sB32 + (uint32_t)(((warpN * 32 + (sub >> 1) * 8 + r8) * LDB + (sub & 1) * 8) * 2);

    float rsum[4][2];
#pragma unroll
    for (int mt = 0; mt < 4; mt++) { rsum[mt][0] = 0.f; rsum[mt][1] = 0.f; }

    __syncthreads();

    int buf = 0;
    for (int tile = bid; tile < NTILES; tile += G) {
        if (producer) {
            // fill next tile into the other buffer while consumers run MMA
            int nxt = tile + G;
            if (nxt < NTILES)
                fill_B(cfv, nxt, sB + (buf ^ 1) * (NTILE * LDB), tid - 256);
        } else {
            // ---- MMA on current buf ----
            float acc[4][4][4];
#pragma unroll
            for (int mt = 0; mt < 4; mt++)
#pragma unroll
                for (int nt = 0; nt < 4; nt++)
#pragma unroll
                    for (int q = 0; q < 4; q++) acc[mt][nt][q] = 0.f;

            const uint32_t bBase = bBase0 + buf * BUFB;
#pragma unroll
            for (int ks = 0; ks < 16; ks++) {
                uint32_t a[4][4], b[4][2];
#pragma unroll
                for (int mt = 0; mt < 4; mt++)
                    ldm4(a[mt][0], a[mt][1], a[mt][2], a[mt][3],
                         aBase + (uint32_t)(mt * 16 * LDA * 2 + ks * 32));
                {
                    uint32_t q0, q1, q2, q3;
                    ldm4(q0, q1, q2, q3, bBase + (uint32_t)(ks * 32));
                    b[0][0] = q0; b[0][1] = q1; b[1][0] = q2; b[1][1] = q3;
                    ldm4(q0, q1, q2, q3, bBase + (uint32_t)(16 * LDB * 2 + ks * 32));
                    b[2][0] = q0; b[2][1] = q1; b[3][0] = q2; b[3][1] = q3;
                }
#pragma unroll
                for (int mt = 0; mt < 4; mt++)
#pragma unroll
                    for (int nt = 0; nt < 4; nt++)
                        mma_bf16(acc[mt][nt], a[mt], b[nt]);
            }

            // ---- epilogue: acc holds logits*log2e -> ex2 + rowsum ----
#pragma unroll
            for (int mt = 0; mt < 4; mt++) {
                float lo = 0.f, hi = 0.f;
#pragma unroll
                for (int nt = 0; nt < 4; nt++) {
                    lo += ex2(acc[mt][nt][0]) + ex2(acc[mt][nt][1]);
                    hi += ex2(acc[mt][nt][2]) + ex2(acc[mt][nt][3]);
                }
                rsum[mt][0] += lo;
                rsum[mt][1] += hi;
            }
        }

        __syncthreads();   // buf consumed by MMA warps + buf^1 fully written
        buf ^= 1;
    }

    // consumer warps reduce across the quad, combine the two warpN halves
    if (!producer) {
#pragma unroll
        for (int mt = 0; mt < 4; mt++)
#pragma unroll
            for (int h = 0; h < 2; h++) {
                float vv = rsum[mt][h];
                vv += __shfl_xor_sync(0xffffffffu, vv, 1);
                vv += __shfl_xor_sync(0xffffffffu, vv, 2);
                if ((lane & 3) == 0)
                    sp[warpN * 256 + warpM * 64 + mt * 16 + h * 8 + (lane >> 2)] = vv;
            }
    }
    __syncthreads();
    if (tid < B_DIM)
        g_partial[tid * GSTRIDE + bid] = sp[tid] + sp[256 + tid];   // transposed [m][g]
}

// ---------------- final reduction (contiguous per-thread rows, MLP-rich) ----------------
__global__ void finalize_kernel(int G, float *__restrict__ out) {
    int m = threadIdx.x;   // 256 threads
    const float4 *row = reinterpret_cast<const float4 *>(g_partial + m * GSTRIDE);
    float s0 = 0.f, s1 = 0.f, s2 = 0.f, s3 = 0.f;
    int g4 = G >> 2;
#pragma unroll 4
    for (int i = 0; i < g4; i++) {
        float4 v = row[i];
        s0 += v.x; s1 += v.y; s2 += v.z; s3 += v.w;
    }
    float S = (s0 + s1) + (s2 + s3);
    for (int g = g4 << 2; g < G; g++) S += g_partial[m * GSTRIDE + g];

    float lt = g_tdot[m];
    float p = expf(lt) / (S + EPS_SM) + EPS_LOG;
    float vv = logf(p);
    __shared__ float red[256];
    red[m] = vv;
    __syncthreads();
#pragma unroll
    for (int s = 128; s > 0; s >>= 1) {
        if (m < s) red[m] += red[m + s];
        __syncthreads();
    }
    if (m == 0) out[0] = -red[0] / (float)B_DIM;
}

// ---------------- launch ----------------
extern "C" void kernel_launch(void *const *d_in, const int *in_sizes, int n_in,
                              void *d_out, int out_size) {
    const float *inputs = (const float *)d_in[0];
    const float *cf     = (const float *)d_in[1];
    // d_in[2] instance_features: unused by the reference loss
    const int *indexes  = (const int *)d_in[3];
    const int *labels   = (const int *)d_in[4];
    float *out          = (float *)d_out;

    int dev = 0;
    cudaGetDevice(&dev);
    int sm = 148;
    cudaDeviceGetAttribute(&sm, cudaDevAttrMultiProcessorCount, dev);
    int G = sm;
    if (G < 1) G = 148;
    if (G > GSTRIDE) G = GSTRIDE;
    if (G > NTILES) G = NTILES;

    const int smemBytes = B_DIM * LDA * 2 + 2 * NTILE * LDB * 2 + 512 * 4;  // 204800
    cudaFuncSetAttribute(gemm_kernel, cudaFuncAttributeMaxDynamicSharedMemorySize, smemBytes);

    prep_inputs_kernel<<<64, 256>>>((const float4 *)inputs);
    targets_kernel<<<32, 256>>>(inputs, cf, indexes, labels);
    gemm_kernel<<<G, 512, smemBytes>>>(cf);
    finalize_kernel<<<1, 256>>>(G, out);
}

// round 6
// speedup vs baseline: 1.3347x; 1.0611x over previous
#include <cuda_runtime.h>
#include <cuda_bf16.h>
#include <cstdint>

// Problem constants
#define B_DIM   256
#define D_DIM   256
#define N_DIM   131072
#define TEMP_INV 20.0f
#define LOG2E   1.4426950408889634f
#define EPS_SM  1e-6f
#define EPS_LOG 1e-6f

#define NTILE   64                  // N columns per CTA tile
#define NTILES  (N_DIM / NTILE)     // 2048
#define LDA     264                 // 256 + 8 pad (bf16 elems)
#define LDB     264
#define GSTRIDE 160                 // per-row stride in g_partial (>= max grid)

// Named barriers: ready[b] = 1+b (producer->consumer), done[b] = 3+b (consumer->producer)
#define BAR_ARRIVE(id) asm volatile("bar.arrive %0, %1;" :: "r"(id), "r"(512) : "memory")
#define BAR_SYNC(id)   asm volatile("bar.sync %0, %1;"   :: "r"(id), "r"(512) : "memory")
#define BAR_SYNC_C(id) asm volatile("bar.sync %0, %1;"   :: "r"(id), "r"(256) : "memory")

// Device scratch
__device__ __align__(16) __nv_bfloat16 g_A[B_DIM * D_DIM];  // inputs * TEMP_INV * LOG2E
__device__ __align__(16) float g_partial[B_DIM * GSTRIDE];  // [m][g]
__device__ float g_tdot[B_DIM];
__device__ int g_done = 0;

// ---------------- helpers ----------------
__device__ __forceinline__ void ldm4(uint32_t &r0, uint32_t &r1, uint32_t &r2, uint32_t &r3,
                                     uint32_t addr) {
    asm volatile("ldmatrix.sync.aligned.m8n8.x4.shared.b16 {%0,%1,%2,%3}, [%4];\n"
                 : "=r"(r0), "=r"(r1), "=r"(r2), "=r"(r3) : "r"(addr));
}

__device__ __forceinline__ void mma_bf16(float *c, const uint32_t *a, const uint32_t *b) {
    asm volatile("mma.sync.aligned.m16n8k16.row.col.f32.bf16.bf16.f32 "
                 "{%0,%1,%2,%3}, {%4,%5,%6,%7}, {%8,%9}, {%0,%1,%2,%3};\n"
                 : "+f"(c[0]), "+f"(c[1]), "+f"(c[2]), "+f"(c[3])
                 : "r"(a[0]), "r"(a[1]), "r"(a[2]), "r"(a[3]), "r"(b[0]), "r"(b[1]));
}

__device__ __forceinline__ float ex2(float x) {
    float y;
    asm("ex2.approx.f32 %0, %1;" : "=f"(y) : "f"(x));
    return y;
}

// ---------------- prep: inputs->bf16 (blocks 0..63) + target dots (blocks 64..95) ----
__global__ void prep_kernel(const float *__restrict__ inputs,
                            const float *__restrict__ cf,
                            const int *__restrict__ indexes,
                            const int *__restrict__ labels) {
    if (blockIdx.x < 64) {
        int i = blockIdx.x * 256 + threadIdx.x;   // 16384 float4s
        const float S = TEMP_INV * LOG2E;
        float4 v = reinterpret_cast<const float4 *>(inputs)[i];
        __nv_bfloat162 lo = __floats2bfloat162_rn(v.x * S, v.y * S);
        __nv_bfloat162 hi = __floats2bfloat162_rn(v.z * S, v.w * S);
        uint2 u;
        u.x = *reinterpret_cast<uint32_t *>(&lo);
        u.y = *reinterpret_cast<uint32_t *>(&hi);
        reinterpret_cast<uint2 *>(g_A)[i] = u;
    } else {
        int lane = threadIdx.x & 31;
        int w = ((blockIdx.x - 64) * 256 + threadIdx.x) >> 5;   // 0..255
        if (w >= B_DIM) return;
        int t = labels[indexes[w]];
        const float4 *a = reinterpret_cast<const float4 *>(inputs + (size_t)w * D_DIM);
        const float4 *b = reinterpret_cast<const float4 *>(cf + (size_t)t * D_DIM);
        float s = 0.f;
#pragma unroll
        for (int i = 0; i < 2; i++) {
            float4 x = a[lane + i * 32];
            float4 y = b[lane + i * 32];
            s += x.x * y.x + x.y * y.y + x.z * y.z + x.w * y.w;
        }
#pragma unroll
        for (int o = 16; o; o >>= 1) s += __shfl_xor_sync(0xffffffffu, s, o);
        if (lane == 0) g_tdot[w] = s * TEMP_INV;
    }
}

// ---------------- producer: load+convert one B tile into smem buffer ----------------
static __device__ __forceinline__ void fill_B(const float4 *__restrict__ cfv, int tile,
                                              __nv_bfloat16 *dB, int ptid) {
    const size_t rowbase = (size_t)tile * NTILE;
#pragma unroll
    for (int it = 0; it < 16; it++) {
        int c = ptid + it * 256;       // 0..4095 float4 chunks
        int r = c >> 6;                // 0..63 (N row in tile)
        int kq = c & 63;               // 0..63 (K quad)
        float4 v = cfv[(rowbase + r) * (D_DIM / 4) + kq];
        __nv_bfloat162 lo = __floats2bfloat162_rn(v.x, v.y);
        __nv_bfloat162 hi = __floats2bfloat162_rn(v.z, v.w);
        uint2 u;
        u.x = *reinterpret_cast<uint32_t *>(&lo);
        u.y = *reinterpret_cast<uint32_t *>(&hi);
        *reinterpret_cast<uint2 *>(dB + r * LDB + kq * 4) = u;
    }
}

// ---------------- fused GEMM + exp + rowsum + last-CTA finalize ----------------
__global__ void __launch_bounds__(512, 1) gemm_kernel(const float *__restrict__ cf,
                                                      float *__restrict__ out, int G) {
    extern __shared__ char smem[];
    __nv_bfloat16 *sA = reinterpret_cast<__nv_bfloat16 *>(smem);                 // 256*264
    __nv_bfloat16 *sB = reinterpret_cast<__nv_bfloat16 *>(smem + B_DIM * LDA * 2);
    float *sp = reinterpret_cast<float *>(smem + B_DIM * LDA * 2 + 2 * NTILE * LDB * 2);
    __shared__ int s_last;

    const int tid = threadIdx.x;
    const int lane = tid & 31;
    const int warp = tid >> 5;
    const bool producer = (warp >= 8);
    const int bid = blockIdx.x;
    const float4 *cfv = reinterpret_cast<const float4 *>(cf);

    const uint32_t sA32 = (uint32_t)__cvta_generic_to_shared(sA);
    const uint32_t sB32 = (uint32_t)__cvta_generic_to_shared(sB);
    const uint32_t BUFB = NTILE * LDB * 2;

    const int warpM = warp & 3;
    const int warpN = (warp >> 2) & 1;
    const int sub = lane >> 3, r8 = lane & 7;
    const uint32_t aBase =
        sA32 + (uint32_t)(((warpM * 64 + (sub & 1) * 8 + r8) * LDA + (sub >> 1) * 8) * 2);
    const uint32_t bBase0 =
        sB32 + (uint32_t)(((warpN * 32 + (sub >> 1) * 8 + r8) * LDB + (sub & 1) * 8) * 2);

    if (producer) {
        const int ptid = tid - 256;
        // prime buffer 0
        fill_B(cfv, bid, sB, ptid);
        BAR_ARRIVE(1);                           // ready[0]
        int i = 1;
        for (int tile = bid + G; tile < NTILES; tile += G, i++) {
            int b = i & 1;
            if (i >= 2) BAR_SYNC(3 + b);         // wait done[b] from fill i-2
            fill_B(cfv, tile, sB + b * (NTILE * LDB), ptid);
            BAR_ARRIVE(1 + b);                   // ready[b]
        }
    } else {
        // load A (pre-scaled bf16) into padded smem
#pragma unroll
        for (int i = 0; i < 32; i++) {
            int idx = tid + i * 256;
            int row = idx >> 5;
            int col = (idx & 31) << 3;
            *reinterpret_cast<uint4 *>(sA + row * LDA + col) =
                reinterpret_cast<const uint4 *>(g_A)[idx];
        }
        BAR_SYNC_C(5);              // consumers-only: A visible

        float rsum[4][2];
#pragma unroll
        for (int mt = 0; mt < 4; mt++) { rsum[mt][0] = 0.f; rsum[mt][1] = 0.f; }

        int i = 0;
        for (int tile = bid; tile < NTILES; tile += G, i++) {
            int b = i & 1;
            BAR_SYNC(1 + b);        // wait ready[b]

            float acc[4][4][4];
#pragma unroll
            for (int mt = 0; mt < 4; mt++)
#pragma unroll
                for (int nt = 0; nt < 4; nt++)
#pragma unroll
                    for (int q = 0; q < 4; q++) acc[mt][nt][q] = 0.f;

            const uint32_t bBase = bBase0 + b * BUFB;
#pragma unroll
            for (int ks = 0; ks < 16; ks++) {
                uint32_t a[4][4], bb[4][2];
#pragma unroll
                for (int mt = 0; mt < 4; mt++)
                    ldm4(a[mt][0], a[mt][1], a[mt][2], a[mt][3],
                         aBase + (uint32_t)(mt * 16 * LDA * 2 + ks * 32));
                {
                    uint32_t q0, q1, q2, q3;
                    ldm4(q0, q1, q2, q3, bBase + (uint32_t)(ks * 32));
                    bb[0][0] = q0; bb[0][1] = q1; bb[1][0] = q2; bb[1][1] = q3;
                    ldm4(q0, q1, q2, q3, bBase + (uint32_t)(16 * LDB * 2 + ks * 32));
                    bb[2][0] = q0; bb[2][1] = q1; bb[3][0] = q2; bb[3][1] = q3;
                }
#pragma unroll
                for (int mt = 0; mt < 4; mt++)
#pragma unroll
                    for (int nt = 0; nt < 4; nt++)
                        mma_bf16(acc[mt][nt], a[mt], bb[nt]);
            }
            BAR_ARRIVE(3 + b);      // done[b] (epilogue off handoff path)

            // epilogue: acc holds logits*log2e -> ex2 + rowsum
#pragma unroll
            for (int mt = 0; mt < 4; mt++) {
                float lo = 0.f, hi = 0.f;
#pragma unroll
                for (int nt = 0; nt < 4; nt++) {
                    lo += ex2(acc[mt][nt][0]) + ex2(acc[mt][nt][1]);
                    hi += ex2(acc[mt][nt][2]) + ex2(acc[mt][nt][3]);
                }
                rsum[mt][0] += lo;
                rsum[mt][1] += hi;
            }
        }

        // reduce across quad, stage per-m sums in sp
#pragma unroll
        for (int mt = 0; mt < 4; mt++)
#pragma unroll
            for (int h = 0; h < 2; h++) {
                float vv = rsum[mt][h];
                vv += __shfl_xor_sync(0xffffffffu, vv, 1);
                vv += __shfl_xor_sync(0xffffffffu, vv, 2);
                if ((lane & 3) == 0)
                    sp[warpN * 256 + warpM * 64 + mt * 16 + h * 8 + (lane >> 2)] = vv;
            }
    }

    __syncthreads();
    if (tid < B_DIM)
        g_partial[tid * GSTRIDE + bid] = sp[tid] + sp[256 + tid];
    __threadfence();
    __syncthreads();
    if (tid == 0) {
        int old = atomicAdd(&g_done, 1);
        s_last = (old == G - 1) ? 1 : 0;
    }
    __syncthreads();

    if (s_last) {
        // final reduction (L2-hot partials)
        float vv = 0.f;
        if (tid < B_DIM) {
            const float4 *row = reinterpret_cast<const float4 *>(g_partial + tid * GSTRIDE);
            float s0 = 0.f, s1 = 0.f, s2 = 0.f, s3 = 0.f;
            int g4 = G >> 2;
#pragma unroll 4
            for (int i = 0; i < g4; i++) {
                float4 v = row[i];
                s0 += v.x; s1 += v.y; s2 += v.z; s3 += v.w;
            }
            float S = (s0 + s1) + (s2 + s3);
            for (int g = g4 << 2; g < G; g++) S += g_partial[tid * GSTRIDE + g];
            float lt = g_tdot[tid];
            vv = logf(expf(lt) / (S + EPS_SM) + EPS_LOG);
        }
        __syncthreads();   // sp reuse safe
        if (tid < B_DIM) sp[tid] = vv;
        __syncthreads();
#pragma unroll
        for (int s = 128; s > 0; s >>= 1) {
            if (tid < s) sp[tid] += sp[tid + s];
            __syncthreads();
        }
        if (tid == 0) {
            out[0] = -sp[0] / (float)B_DIM;
            g_done = 0;   // reset for next graph replay
        }
    }
}

// ---------------- launch ----------------
extern "C" void kernel_launch(void *const *d_in, const int *in_sizes, int n_in,
                              void *d_out, int out_size) {
    const float *inputs = (const float *)d_in[0];
    const float *cf     = (const float *)d_in[1];
    // d_in[2] instance_features: unused by the reference loss
    const int *indexes  = (const int *)d_in[3];
    const int *labels   = (const int *)d_in[4];
    float *out          = (float *)d_out;

    int dev = 0;
    cudaGetDevice(&dev);
    int sm = 148;
    cudaDeviceGetAttribute(&sm, cudaDevAttrMultiProcessorCount, dev);
    int G = sm;
    if (G < 1) G = 148;
    if (G > GSTRIDE) G = GSTRIDE;
    if (G > NTILES) G = NTILES;

    const int smemBytes = B_DIM * LDA * 2 + 2 * NTILE * LDB * 2 + 512 * 4;  // 204800
    cudaFuncSetAttribute(gemm_kernel, cudaFuncAttributeMaxDynamicSharedMemorySize, smemBytes);

    prep_kernel<<<96, 256>>>(inputs, cf, indexes, labels);
    gemm_kernel<<<G, 512, smemBytes>>>(cf, out, G);
}